// round 15
// baseline (speedup 1.0000x reference)
#include <cuda_runtime.h>
#include <cuda_fp16.h>
#include <cstdint>

// Problem constants
constexpr int Bb   = 2;
constexpr int T    = 2048;
constexpr int Cc   = 1024;
constexpr int H    = 16;
constexpr int D    = 64;
constexpr int HD   = H * D;          // 1024
constexpr int QKV3 = 3 * HD;         // 3072
constexpr int M_ROWS = Bb * T;       // 4096

// Scratch (no cudaMalloc allowed)
__device__ __half g_xh[(size_t)M_ROWS * Cc];
__device__ __half g_wqh[(size_t)QKV3 * Cc];
__device__ __half g_wph[(size_t)HD * HD];
__device__ __half g_qkvh[(size_t)M_ROWS * QKV3];
__device__ __half g_attnh[(size_t)M_ROWS * HD];

// ---------------------------------------------------------------------------
// helpers
// ---------------------------------------------------------------------------
__device__ __forceinline__ uint32_t smem_u32(const void* p) {
    uint32_t a;
    asm("{ .reg .u64 t; cvta.to.shared.u64 t, %1; cvt.u32.u64 %0, t; }"
        : "=r"(a) : "l"(p));
    return a;
}
__device__ __forceinline__ void cp16(uint32_t dst, const void* src) {
    asm volatile("cp.async.cg.shared.global [%0], [%1], 16;"
                 :: "r"(dst), "l"(src) : "memory");
}
#define CP_COMMIT() asm volatile("cp.async.commit_group;" ::: "memory")
#define CP_WAIT1()  asm volatile("cp.async.wait_group 1;"  ::: "memory")
#define CP_WAIT0()  asm volatile("cp.async.wait_group 0;"  ::: "memory")

__device__ __forceinline__ void ldsm_x4(uint32_t& r0, uint32_t& r1,
                                        uint32_t& r2, uint32_t& r3, uint32_t addr) {
    asm volatile("ldmatrix.sync.aligned.m8n8.x4.shared.b16 {%0,%1,%2,%3}, [%4];"
                 : "=r"(r0), "=r"(r1), "=r"(r2), "=r"(r3) : "r"(addr));
}
__device__ __forceinline__ void ldsm_x4_t(uint32_t& r0, uint32_t& r1,
                                          uint32_t& r2, uint32_t& r3, uint32_t addr) {
    asm volatile("ldmatrix.sync.aligned.m8n8.x4.trans.shared.b16 {%0,%1,%2,%3}, [%4];"
                 : "=r"(r0), "=r"(r1), "=r"(r2), "=r"(r3) : "r"(addr));
}

// fp16 m16n8k16, fp32 accumulate
__device__ __forceinline__ void mma16(float& d0, float& d1, float& d2, float& d3,
                                      uint32_t a0, uint32_t a1, uint32_t a2, uint32_t a3,
                                      uint32_t b0, uint32_t b1) {
    asm volatile(
        "mma.sync.aligned.m16n8k16.row.col.f32.f16.f16.f32 "
        "{%0,%1,%2,%3}, {%4,%5,%6,%7}, {%8,%9}, {%0,%1,%2,%3};\n"
        : "+f"(d0), "+f"(d1), "+f"(d2), "+f"(d3)
        : "r"(a0), "r"(a1), "r"(a2), "r"(a3), "r"(b0), "r"(b1));
}
__device__ __forceinline__ uint32_t packh2(float a, float b) {
    __half2 h = __floats2half2_rn(a, b);
    return *(uint32_t*)&h;
}

// ---------------------------------------------------------------------------
// fused fp32 -> fp16 conversion for x, W_qkv, W_proj (grid-stride float4)
// ---------------------------------------------------------------------------
__global__ __launch_bounds__(256) void cvt_all(
    const float* __restrict__ x,  __half* __restrict__ xh,
    const float* __restrict__ wq, __half* __restrict__ wqh,
    const float* __restrict__ wp, __half* __restrict__ wph)
{
    constexpr int n1 = M_ROWS * Cc / 4;
    constexpr int n2 = QKV3 * Cc / 4;
    constexpr int n3 = HD * HD / 4;
    constexpr int total = n1 + n2 + n3;
    int i = blockIdx.x * blockDim.x + threadIdx.x;
    const int stride = gridDim.x * blockDim.x;
    for (; i < total; i += stride) {
        const float* s; __half* d; int j;
        if (i < n1)            { s = x;  d = xh;  j = i; }
        else if (i < n1 + n2)  { s = wq; d = wqh; j = i - n1; }
        else                   { s = wp; d = wph; j = i - n1 - n2; }
        float4 v = *(const float4*)(s + 4 * (size_t)j);
        __half2 h0 = __floats2half2_rn(v.x, v.y);
        __half2 h1 = __floats2half2_rn(v.z, v.w);
        uint2 w = { *(uint32_t*)&h0, *(uint32_t*)&h1 };
        *(uint2*)(d + 4 * (size_t)j) = w;
    }
}

// ---------------------------------------------------------------------------
// fp16 GEMM, cp.async 3-stage pipeline + ldmatrix: C = A @ Bm^T + bias.
// CTA tile 128x128, BK=64 (halved barrier cadence vs BK=32).
// 256 threads = 8 warps, warp tile 64x32, 2 CTAs/SM.
// smem row stride 36 words (mod 32 = 4 -> LDSM conflict-free, same as attn QS).
// ---------------------------------------------------------------------------
constexpr int GSH    = 36;                        // words per 64-half row
constexpr int NSTAGE = 3;
constexpr int STAGE_TOT_W = 256 * GSH;            // A(128)+B(128) rows per stage
constexpr int A_W = 128 * GSH;
constexpr int GEMM_SMEM = NSTAGE * STAGE_TOT_W * 4;   // 110592 B

template <bool HALF_OUT>
__global__ __launch_bounds__(256, 2) void gemm_f16(
    int M, int N, int K,
    const __half* __restrict__ A,
    const __half* __restrict__ Bm,
    const float* __restrict__ bias,
    void* __restrict__ Cout)
{
    extern __shared__ __align__(16) uint32_t sh[];
    const uint32_t sbase = smem_u32(sh);

    const int tid  = threadIdx.x;
    const int lane = tid & 31;
    const int wid  = tid >> 5;
    const int wm   = (wid & 1) * 64;
    const int wn   = (wid >> 1) * 32;
    const int m0   = blockIdx.y * 128;
    const int n0   = blockIdx.x * 128;
    const int lr   = lane >> 2;
    const int lc   = lane & 3;
    const int sub  = lane >> 3;
    const int l8   = lane & 7;
    const uint32_t aoff = (uint32_t)((((sub & 1) * 8 + l8) * GSH + (sub >> 1) * 4) * 4);
    const uint32_t boff = (uint32_t)((((sub >> 1) * 8 + l8) * GSH + (sub & 1) * 4) * 4);

    float acc[4][4][4] = {};

    const int nk = K >> 6;   // BK = 64

    auto issue = [&](int i, int s) {
        const uint32_t stb = sbase + (uint32_t)(s * STAGE_TOT_W) * 4;
        // A: 128 rows x 8 groups of 16B  (1024 slots / 256 thr = 4 each)
#pragma unroll
        for (int p = 0; p < 4; p++) {
            const int slot = tid + p * 256;
            const int r = slot & 127, g = slot >> 7;        // g: 0..7
            cp16(stb + (uint32_t)(r * GSH + g * 4) * 4,
                 A + (size_t)(m0 + r) * K + i * 64 + g * 8);
        }
#pragma unroll
        for (int p = 0; p < 4; p++) {
            const int slot = tid + p * 256;
            const int r = slot & 127, g = slot >> 7;
            cp16(stb + (uint32_t)(A_W + r * GSH + g * 4) * 4,
                 Bm + (size_t)(n0 + r) * K + i * 64 + g * 8);
        }
        CP_COMMIT();
    };

    issue(0, 0);
    if (nk > 1) issue(1, 1);

    int s = 0;
    for (int i = 0; i < nk; i++) {
        CP_WAIT1();
        __syncthreads();

        const int sn = (s + 2 >= NSTAGE) ? s + 2 - NSTAGE : s + 2;
        if (i + 2 < nk) issue(i + 2, sn);

        const uint32_t Ab = sbase + (uint32_t)(s * STAGE_TOT_W) * 4;
        const uint32_t Bb2 = Ab + (uint32_t)A_W * 4;
#pragma unroll
        for (int c = 0; c < 4; c++) {          // four k16 chunks per BK=64
            uint32_t a[4][4];
#pragma unroll
            for (int ii = 0; ii < 4; ii++)
                ldsm_x4(a[ii][0], a[ii][1], a[ii][2], a[ii][3],
                        Ab + aoff + (uint32_t)(((wm + ii * 16) * GSH + c * 8) * 4));
#pragma unroll
            for (int jj = 0; jj < 2; jj++) {
                uint32_t b0, b1, b2, b3;
                ldsm_x4(b0, b1, b2, b3,
                        Bb2 + boff + (uint32_t)(((wn + jj * 16) * GSH + c * 8) * 4));
#pragma unroll
                for (int ii = 0; ii < 4; ii++) {
                    mma16(acc[ii][2 * jj][0], acc[ii][2 * jj][1],
                          acc[ii][2 * jj][2], acc[ii][2 * jj][3],
                          a[ii][0], a[ii][1], a[ii][2], a[ii][3], b0, b1);
                    mma16(acc[ii][2 * jj + 1][0], acc[ii][2 * jj + 1][1],
                          acc[ii][2 * jj + 1][2], acc[ii][2 * jj + 1][3],
                          a[ii][0], a[ii][1], a[ii][2], a[ii][3], b2, b3);
                }
            }
        }
        s = (s + 1 >= NSTAGE) ? 0 : s + 1;
    }

#pragma unroll
    for (int ii = 0; ii < 4; ii++) {
        const int r = m0 + wm + ii * 16 + lr;
#pragma unroll
        for (int j = 0; j < 4; j++) {
            const int c = n0 + wn + j * 8 + 2 * lc;
            const float2 bi = *(const float2*)&bias[c];
            const float v00 = acc[ii][j][0] + bi.x, v01 = acc[ii][j][1] + bi.y;
            const float v10 = acc[ii][j][2] + bi.x, v11 = acc[ii][j][3] + bi.y;
            if (HALF_OUT) {
                __half* Ch = (__half*)Cout;
                __half2 h0 = __floats2half2_rn(v00, v01);
                __half2 h1 = __floats2half2_rn(v10, v11);
                *(__half2*)&Ch[(size_t)r * N + c] = h0;
                *(__half2*)&Ch[(size_t)(r + 8) * N + c] = h1;
            } else {
                float* Cf = (float*)Cout;
                float2 f0 = { v00, v01 }, f1 = { v10, v11 };
                *(float2*)&Cf[(size_t)r * N + c] = f0;
                *(float2*)&Cf[(size_t)(r + 8) * N + c] = f1;
            }
        }
    }
}

// ---------------------------------------------------------------------------
// Flash attention with sink, all-fp16 MMA, register-resident P.
// Br=128 (256 threads, 8 warps x 16 rows). K/V pipeline step = 128 kv rows,
// double-buffered via cp.async (one __syncthreads per 128 kv rows).
// (unchanged from R11 — verified)
// ---------------------------------------------------------------------------
constexpr int QS = 36;
constexpr int ATTN_STAGE_W = 2 * 128 * QS;                       // K+V words/stage
constexpr int ATTN_SMEM = (128 * QS + 2 * ATTN_STAGE_W) * 4;     // 92160 B

__global__ __launch_bounds__(256, 2) void attn_f16(
    const __half* __restrict__ qkv,
    const float* __restrict__ sink_logit,
    __half* __restrict__ attn_out)
{
    extern __shared__ __align__(16) uint32_t dyn[];
    uint32_t* Qs = dyn;                        // [128][QS]
    const uint32_t sbase = smem_u32(dyn);

    const int qt  = (T / 128 - 1) - blockIdx.x;   // heavy tiles first
    const int h   = blockIdx.y;
    const int b   = blockIdx.z;
    const int tid = threadIdx.x;
    const int lane = tid & 31;
    const int wid  = tid >> 5;
    const int t0   = qt * 128;
    const int mb   = wid * 16;
    const int lr   = lane >> 2;
    const int lc   = lane & 3;
    const int sub  = lane >> 3;
    const int l8   = lane & 7;
    const uint32_t qoff = (uint32_t)((((sub & 1) * 8 + l8) * QS + (sub >> 1) * 4) * 4);
    const uint32_t koff = (uint32_t)((((sub >> 1) * 8 + l8) * QS + (sub & 1) * 4) * 4);
    const __half2 SC2 = __float2half2_rn(0.125f);

    auto kstage = [&](int s) -> uint32_t {
        return sbase + (uint32_t)(128 * QS + s * ATTN_STAGE_W) * 4;
    };
    auto issue_kv = [&](int kt, int s) {
        const uint32_t kb_ = kstage(s);
        const uint32_t vb_ = kb_ + (uint32_t)(128 * QS) * 4;
        const int kv0 = kt * 128;
#pragma unroll
        for (int p = 0; p < 4; p++) {
            const int slot = tid + p * 256;
            const int r = slot >> 3, g = slot & 7;
            const __half* src = qkv + (size_t)(b * T + kv0 + r) * QKV3 + h * D + g * 8;
            const uint32_t doff = (uint32_t)(r * QS + g * 4) * 4;
            cp16(kb_ + doff, src + HD);
            cp16(vb_ + doff, src + 2 * HD);
        }
        CP_COMMIT();
    };

#pragma unroll
    for (int p = 0; p < 4; p++) {
        const int slot = tid + p * 256;
        const int r = slot >> 3, g = slot & 7;
        uint4 v = *(const uint4*)&qkv[(size_t)(b * T + t0 + r) * QKV3 + h * D + g * 8];
        __half2* hp = (__half2*)&v;
        hp[0] = __hmul2(hp[0], SC2); hp[1] = __hmul2(hp[1], SC2);
        hp[2] = __hmul2(hp[2], SC2); hp[3] = __hmul2(hp[3], SC2);
        *(uint4*)&Qs[r * QS + g * 4] = v;
    }

    const float sink = sink_logit[h];
    float m0v = sink, m1v = sink, l0 = 1.f, l1 = 1.f;
    float o[8][4] = {};

    const int nkt = qt + 1;
    issue_kv(0, 0);

    for (int kt = 0; kt < nkt; kt++) {
        CP_WAIT0();
        __syncthreads();
        if (kt + 1 < nkt) issue_kv(kt + 1, (kt + 1) & 1);

        const uint32_t Kb = kstage(kt & 1);
        const uint32_t Vb = Kb + (uint32_t)(128 * QS) * 4;

#pragma unroll
        for (int c2 = 0; c2 < 2; c2++) {
            const int kb = kt * 128 + c2 * 64;
            if (kb > t0 + mb + 15) continue;
            const uint32_t Kc = Kb + (uint32_t)(c2 * 64 * QS) * 4;
            const uint32_t Vc = Vb + (uint32_t)(c2 * 64 * QS) * 4;

            float s[8][4] = {};
#pragma unroll
            for (int c = 0; c < 4; c++) {
                uint32_t a0, a1, a2, a3;
                ldsm_x4(a0, a1, a2, a3,
                        sbase + qoff + (uint32_t)((mb * QS + c * 8) * 4));
#pragma unroll
                for (int jj = 0; jj < 4; jj++) {
                    uint32_t b0, b1, b2, b3;
                    ldsm_x4(b0, b1, b2, b3,
                            Kc + koff + (uint32_t)((jj * 16 * QS + c * 8) * 4));
                    mma16(s[2 * jj][0], s[2 * jj][1], s[2 * jj][2], s[2 * jj][3],
                          a0, a1, a2, a3, b0, b1);
                    mma16(s[2 * jj + 1][0], s[2 * jj + 1][1], s[2 * jj + 1][2], s[2 * jj + 1][3],
                          a0, a1, a2, a3, b2, b3);
                }
            }

            if (kb + 63 > t0 + mb) {
                const int qr0 = t0 + mb + lr, qr1 = qr0 + 8;
#pragma unroll
                for (int j = 0; j < 8; j++) {
                    const int c = kb + j * 8 + 2 * lc;
                    if (c     > qr0) s[j][0] = -1e30f;
                    if (c + 1 > qr0) s[j][1] = -1e30f;
                    if (c     > qr1) s[j][2] = -1e30f;
                    if (c + 1 > qr1) s[j][3] = -1e30f;
                }
            }

            float rmax0 = -1e30f, rmax1 = -1e30f;
#pragma unroll
            for (int j = 0; j < 8; j++) {
                rmax0 = fmaxf(rmax0, fmaxf(s[j][0], s[j][1]));
                rmax1 = fmaxf(rmax1, fmaxf(s[j][2], s[j][3]));
            }
            rmax0 = fmaxf(rmax0, __shfl_xor_sync(~0u, rmax0, 1));
            rmax0 = fmaxf(rmax0, __shfl_xor_sync(~0u, rmax0, 2));
            rmax1 = fmaxf(rmax1, __shfl_xor_sync(~0u, rmax1, 1));
            rmax1 = fmaxf(rmax1, __shfl_xor_sync(~0u, rmax1, 2));

            const float mn0 = fmaxf(m0v, rmax0), mn1 = fmaxf(m1v, rmax1);
            const float sc0 = __expf(m0v - mn0), sc1 = __expf(m1v - mn1);
            float rs0 = 0.f, rs1 = 0.f;
#pragma unroll
            for (int j = 0; j < 8; j++) {
                s[j][0] = __expf(s[j][0] - mn0);
                s[j][1] = __expf(s[j][1] - mn0);
                s[j][2] = __expf(s[j][2] - mn1);
                s[j][3] = __expf(s[j][3] - mn1);
                rs0 += s[j][0] + s[j][1];
                rs1 += s[j][2] + s[j][3];
            }
            rs0 += __shfl_xor_sync(~0u, rs0, 1); rs0 += __shfl_xor_sync(~0u, rs0, 2);
            rs1 += __shfl_xor_sync(~0u, rs1, 1); rs1 += __shfl_xor_sync(~0u, rs1, 2);
            l0 = l0 * sc0 + rs0;  l1 = l1 * sc1 + rs1;
            m0v = mn0;  m1v = mn1;

            uint32_t pa[4][4];
#pragma unroll
            for (int u = 0; u < 4; u++) {
                pa[u][0] = packh2(s[2 * u][0],     s[2 * u][1]);
                pa[u][1] = packh2(s[2 * u][2],     s[2 * u][3]);
                pa[u][2] = packh2(s[2 * u + 1][0], s[2 * u + 1][1]);
                pa[u][3] = packh2(s[2 * u + 1][2], s[2 * u + 1][3]);
            }

#pragma unroll
            for (int j = 0; j < 8; j++) {
                o[j][0] *= sc0; o[j][1] *= sc0;
                o[j][2] *= sc1; o[j][3] *= sc1;
            }

#pragma unroll
            for (int u = 0; u < 4; u++) {
#pragma unroll
                for (int dd = 0; dd < 4; dd++) {
                    uint32_t b0, b1, b2, b3;
                    ldsm_x4_t(b0, b1, b2, b3,
                        Vc + (uint32_t)(((u * 16 + (sub & 1) * 8 + l8) * QS) * 4
                                        + (dd * 16 + (sub >> 1) * 8) * 2));
                    mma16(o[2 * dd][0], o[2 * dd][1], o[2 * dd][2], o[2 * dd][3],
                          pa[u][0], pa[u][1], pa[u][2], pa[u][3], b0, b1);
                    mma16(o[2 * dd + 1][0], o[2 * dd + 1][1], o[2 * dd + 1][2], o[2 * dd + 1][3],
                          pa[u][0], pa[u][1], pa[u][2], pa[u][3], b2, b3);
                }
            }
        }
    }

    const float inv0 = 1.f / l0, inv1 = 1.f / l1;
#pragma unroll
    for (int j = 0; j < 8; j++) {
        const int c = h * D + j * 8 + 2 * lc;
        __half2 h0 = __floats2half2_rn(o[j][0] * inv0, o[j][1] * inv0);
        *(__half2*)&attn_out[(size_t)(b * T + t0 + mb + lr) * HD + c] = h0;
        __half2 h1 = __floats2half2_rn(o[j][2] * inv1, o[j][3] * inv1);
        *(__half2*)&attn_out[(size_t)(b * T + t0 + mb + 8 + lr) * HD + c] = h1;
    }
}

// ---------------------------------------------------------------------------
// Launch
// ---------------------------------------------------------------------------
extern "C" void kernel_launch(void* const* d_in, const int* in_sizes, int n_in,
                              void* d_out, int out_size)
{
    const float* x      = (const float*)d_in[0];
    const float* W_qkv  = (const float*)d_in[1];
    const float* b_qkv  = (const float*)d_in[2];
    const float* W_proj = (const float*)d_in[3];
    const float* b_proj = (const float*)d_in[4];
    const float* sink   = (const float*)d_in[5];
    float* out = (float*)d_out;

    __half *xh, *wqh, *wph, *qkvh, *attnh;
    cudaGetSymbolAddress((void**)&xh,    g_xh);
    cudaGetSymbolAddress((void**)&wqh,   g_wqh);
    cudaGetSymbolAddress((void**)&wph,   g_wph);
    cudaGetSymbolAddress((void**)&qkvh,  g_qkvh);
    cudaGetSymbolAddress((void**)&attnh, g_attnh);

    cudaFuncSetAttribute((const void*)gemm_f16<true>,
                         cudaFuncAttributeMaxDynamicSharedMemorySize, GEMM_SMEM);
    cudaFuncSetAttribute((const void*)gemm_f16<false>,
                         cudaFuncAttributeMaxDynamicSharedMemorySize, GEMM_SMEM);
    cudaFuncSetAttribute(attn_f16,
                         cudaFuncAttributeMaxDynamicSharedMemorySize, ATTN_SMEM);

    // 0) fused fp32 -> fp16 conversions
    cvt_all<<<2048, 256>>>(x, xh, W_qkv, wqh, W_proj, wph);

    // 1) QKV GEMM (fp16 in/out): BK=64, 8 warps/CTA
    gemm_f16<true><<<dim3(QKV3 / 128, M_ROWS / 128), 256, GEMM_SMEM>>>(
        M_ROWS, QKV3, Cc, xh, wqh, b_qkv, qkvh);

    // 2) Flash attention with sink -> fp16 (4096,1024)
    attn_f16<<<dim3(T / 128, H, Bb), 256, ATTN_SMEM>>>(qkvh, sink, attnh);

    // 3) Proj GEMM (fp16 in, fp32 out): BK=64, 8 warps/CTA
    gemm_f16<false><<<dim3(HD / 128, M_ROWS / 128), 256, GEMM_SMEM>>>(
        M_ROWS, HD, HD, attnh, wph, b_proj, out);
}

// round 16
// speedup vs baseline: 1.0610x; 1.0610x over previous
#include <cuda_runtime.h>
#include <cuda_fp16.h>
#include <cstdint>

// Problem constants
constexpr int Bb   = 2;
constexpr int T    = 2048;
constexpr int Cc   = 1024;
constexpr int H    = 16;
constexpr int D    = 64;
constexpr int HD   = H * D;          // 1024
constexpr int QKV3 = 3 * HD;         // 3072
constexpr int M_ROWS = Bb * T;       // 4096

// Scratch (no cudaMalloc allowed)
__device__ __half g_xh[(size_t)M_ROWS * Cc];
__device__ __half g_wqh[(size_t)QKV3 * Cc];
__device__ __half g_wph[(size_t)HD * HD];
__device__ __half g_qkvh[(size_t)M_ROWS * QKV3];
__device__ __half g_attnh[(size_t)M_ROWS * HD];

// ---------------------------------------------------------------------------
// helpers
// ---------------------------------------------------------------------------
__device__ __forceinline__ uint32_t smem_u32(const void* p) {
    uint32_t a;
    asm("{ .reg .u64 t; cvta.to.shared.u64 t, %1; cvt.u32.u64 %0, t; }"
        : "=r"(a) : "l"(p));
    return a;
}
__device__ __forceinline__ void cp16(uint32_t dst, const void* src) {
    asm volatile("cp.async.cg.shared.global [%0], [%1], 16;"
                 :: "r"(dst), "l"(src) : "memory");
}
#define CP_COMMIT() asm volatile("cp.async.commit_group;" ::: "memory")
#define CP_WAIT1()  asm volatile("cp.async.wait_group 1;"  ::: "memory")
#define CP_WAIT0()  asm volatile("cp.async.wait_group 0;"  ::: "memory")

__device__ __forceinline__ void ldsm_x4(uint32_t& r0, uint32_t& r1,
                                        uint32_t& r2, uint32_t& r3, uint32_t addr) {
    asm volatile("ldmatrix.sync.aligned.m8n8.x4.shared.b16 {%0,%1,%2,%3}, [%4];"
                 : "=r"(r0), "=r"(r1), "=r"(r2), "=r"(r3) : "r"(addr));
}
__device__ __forceinline__ void ldsm_x4_t(uint32_t& r0, uint32_t& r1,
                                          uint32_t& r2, uint32_t& r3, uint32_t addr) {
    asm volatile("ldmatrix.sync.aligned.m8n8.x4.trans.shared.b16 {%0,%1,%2,%3}, [%4];"
                 : "=r"(r0), "=r"(r1), "=r"(r2), "=r"(r3) : "r"(addr));
}

// fp16 m16n8k16, fp32 accumulate
__device__ __forceinline__ void mma16(float& d0, float& d1, float& d2, float& d3,
                                      uint32_t a0, uint32_t a1, uint32_t a2, uint32_t a3,
                                      uint32_t b0, uint32_t b1) {
    asm volatile(
        "mma.sync.aligned.m16n8k16.row.col.f32.f16.f16.f32 "
        "{%0,%1,%2,%3}, {%4,%5,%6,%7}, {%8,%9}, {%0,%1,%2,%3};\n"
        : "+f"(d0), "+f"(d1), "+f"(d2), "+f"(d3)
        : "r"(a0), "r"(a1), "r"(a2), "r"(a3), "r"(b0), "r"(b1));
}
__device__ __forceinline__ uint32_t packh2(float a, float b) {
    __half2 h = __floats2half2_rn(a, b);
    return *(uint32_t*)&h;
}

// ---------------------------------------------------------------------------
// fused fp32 -> fp16 conversion for x, W_qkv, W_proj (grid-stride float4)
// ---------------------------------------------------------------------------
__global__ __launch_bounds__(256) void cvt_all(
    const float* __restrict__ x,  __half* __restrict__ xh,
    const float* __restrict__ wq, __half* __restrict__ wqh,
    const float* __restrict__ wp, __half* __restrict__ wph)
{
    constexpr int n1 = M_ROWS * Cc / 4;
    constexpr int n2 = QKV3 * Cc / 4;
    constexpr int n3 = HD * HD / 4;
    constexpr int total = n1 + n2 + n3;
    int i = blockIdx.x * blockDim.x + threadIdx.x;
    const int stride = gridDim.x * blockDim.x;
    for (; i < total; i += stride) {
        const float* s; __half* d; int j;
        if (i < n1)            { s = x;  d = xh;  j = i; }
        else if (i < n1 + n2)  { s = wq; d = wqh; j = i - n1; }
        else                   { s = wp; d = wph; j = i - n1 - n2; }
        float4 v = *(const float4*)(s + 4 * (size_t)j);
        __half2 h0 = __floats2half2_rn(v.x, v.y);
        __half2 h1 = __floats2half2_rn(v.z, v.w);
        uint2 w = { *(uint32_t*)&h0, *(uint32_t*)&h1 };
        *(uint2*)(d + 4 * (size_t)j) = w;
    }
}

// ---------------------------------------------------------------------------
// fp16 GEMM, cp.async 3-stage pipeline + ldmatrix (R14 verified config).
// CTA tile 128x128, BK=32, 256 threads = 8 warps, warp tile 64x32, 2 CTAs/SM.
// ---------------------------------------------------------------------------
constexpr int GSH    = 20;
constexpr int NSTAGE = 3;
constexpr int STAGE_TOT_W = 256 * GSH;            // A(128)+B(128) rows per stage
constexpr int A_W = 128 * GSH;
constexpr int GEMM_SMEM = NSTAGE * STAGE_TOT_W * 4;   // 61440 B

template <bool HALF_OUT>
__global__ __launch_bounds__(256, 2) void gemm_f16(
    int M, int N, int K,
    const __half* __restrict__ A,
    const __half* __restrict__ Bm,
    const float* __restrict__ bias,
    void* __restrict__ Cout)
{
    extern __shared__ __align__(16) uint32_t sh[];
    const uint32_t sbase = smem_u32(sh);

    const int tid  = threadIdx.x;
    const int lane = tid & 31;
    const int wid  = tid >> 5;
    const int wm   = (wid & 1) * 64;
    const int wn   = (wid >> 1) * 32;
    const int m0   = blockIdx.y * 128;
    const int n0   = blockIdx.x * 128;
    const int lr   = lane >> 2;
    const int lc   = lane & 3;
    const int sub  = lane >> 3;
    const int l8   = lane & 7;
    const uint32_t aoff = (uint32_t)((((sub & 1) * 8 + l8) * GSH + (sub >> 1) * 4) * 4);
    const uint32_t boff = (uint32_t)((((sub >> 1) * 8 + l8) * GSH + (sub & 1) * 4) * 4);

    float acc[4][4][4] = {};

    const int nk = K >> 5;

    auto issue = [&](int i, int s) {
        const uint32_t stb = sbase + (uint32_t)(s * STAGE_TOT_W) * 4;
#pragma unroll
        for (int p = 0; p < 2; p++) {
            const int slot = tid + p * 256;
            const int r = slot & 127, g = (slot >> 7) & 3;
            cp16(stb + (uint32_t)(r * GSH + g * 4) * 4,
                 A + (size_t)(m0 + r) * K + i * 32 + g * 8);
        }
#pragma unroll
        for (int p = 0; p < 2; p++) {
            const int slot = tid + p * 256;
            const int r = slot & 127, g = (slot >> 7) & 3;
            cp16(stb + (uint32_t)(A_W + r * GSH + g * 4) * 4,
                 Bm + (size_t)(n0 + r) * K + i * 32 + g * 8);
        }
        CP_COMMIT();
    };

    issue(0, 0);
    if (nk > 1) issue(1, 1);

    int s = 0;
    for (int i = 0; i < nk; i++) {
        CP_WAIT1();
        __syncthreads();

        const int sn = (s + 2 >= NSTAGE) ? s + 2 - NSTAGE : s + 2;
        if (i + 2 < nk) issue(i + 2, sn);

        const uint32_t Ab = sbase + (uint32_t)(s * STAGE_TOT_W) * 4;
        const uint32_t Bb2 = Ab + (uint32_t)A_W * 4;
#pragma unroll
        for (int c = 0; c < 2; c++) {
            uint32_t a[4][4];
#pragma unroll
            for (int ii = 0; ii < 4; ii++)
                ldsm_x4(a[ii][0], a[ii][1], a[ii][2], a[ii][3],
                        Ab + aoff + (uint32_t)(((wm + ii * 16) * GSH + c * 8) * 4));
#pragma unroll
            for (int jj = 0; jj < 2; jj++) {
                uint32_t b0, b1, b2, b3;
                ldsm_x4(b0, b1, b2, b3,
                        Bb2 + boff + (uint32_t)(((wn + jj * 16) * GSH + c * 8) * 4));
#pragma unroll
                for (int ii = 0; ii < 4; ii++) {
                    mma16(acc[ii][2 * jj][0], acc[ii][2 * jj][1],
                          acc[ii][2 * jj][2], acc[ii][2 * jj][3],
                          a[ii][0], a[ii][1], a[ii][2], a[ii][3], b0, b1);
                    mma16(acc[ii][2 * jj + 1][0], acc[ii][2 * jj + 1][1],
                          acc[ii][2 * jj + 1][2], acc[ii][2 * jj + 1][3],
                          a[ii][0], a[ii][1], a[ii][2], a[ii][3], b2, b3);
                }
            }
        }
        s = (s + 1 >= NSTAGE) ? 0 : s + 1;
    }

#pragma unroll
    for (int ii = 0; ii < 4; ii++) {
        const int r = m0 + wm + ii * 16 + lr;
#pragma unroll
        for (int j = 0; j < 4; j++) {
            const int c = n0 + wn + j * 8 + 2 * lc;
            const float2 bi = *(const float2*)&bias[c];
            const float v00 = acc[ii][j][0] + bi.x, v01 = acc[ii][j][1] + bi.y;
            const float v10 = acc[ii][j][2] + bi.x, v11 = acc[ii][j][3] + bi.y;
            if (HALF_OUT) {
                __half* Ch = (__half*)Cout;
                __half2 h0 = __floats2half2_rn(v00, v01);
                __half2 h1 = __floats2half2_rn(v10, v11);
                *(__half2*)&Ch[(size_t)r * N + c] = h0;
                *(__half2*)&Ch[(size_t)(r + 8) * N + c] = h1;
            } else {
                float* Cf = (float*)Cout;
                float2 f0 = { v00, v01 }, f1 = { v10, v11 };
                *(float2*)&Cf[(size_t)r * N + c] = f0;
                *(float2*)&Cf[(size_t)(r + 8) * N + c] = f1;
            }
        }
    }
}

// ---------------------------------------------------------------------------
// Flash attention with sink, all-fp16 MMA, register-resident P.
// COST-PAIRED CTAs: CTA x processes q-tiles (15-x) then (x) — every CTA costs
// exactly 17 kv-tile units -> 256 uniform CTAs, one balanced wave at 2/SM.
// Br=128 (256 threads, 8 warps x 16 rows); kv step 128 rows, cp.async db.
// ---------------------------------------------------------------------------
constexpr int QS = 36;
constexpr int ATTN_STAGE_W = 2 * 128 * QS;                       // K+V words/stage
constexpr int ATTN_SMEM = (128 * QS + 2 * ATTN_STAGE_W) * 4;     // 92160 B
constexpr int NQT = T / 128;                                     // 16 q-tiles

__global__ __launch_bounds__(256, 2) void attn_f16(
    const __half* __restrict__ qkv,
    const float* __restrict__ sink_logit,
    __half* __restrict__ attn_out)
{
    extern __shared__ __align__(16) uint32_t dyn[];
    uint32_t* Qs = dyn;                        // [128][QS]
    const uint32_t sbase = smem_u32(dyn);

    const int h   = blockIdx.y;
    const int b   = blockIdx.z;
    const int tid = threadIdx.x;
    const int lane = tid & 31;
    const int wid  = tid >> 5;
    const int mb   = wid * 16;
    const int lr   = lane >> 2;
    const int lc   = lane & 3;
    const int sub  = lane >> 3;
    const int l8   = lane & 7;
    const uint32_t qoff = (uint32_t)((((sub & 1) * 8 + l8) * QS + (sub >> 1) * 4) * 4);
    const uint32_t koff = (uint32_t)((((sub >> 1) * 8 + l8) * QS + (sub & 1) * 4) * 4);
    const __half2 SC2 = __float2half2_rn(0.125f);
    const float sink = sink_logit[h];

    auto kstage = [&](int s) -> uint32_t {
        return sbase + (uint32_t)(128 * QS + s * ATTN_STAGE_W) * 4;
    };
    auto issue_kv = [&](int kt, int s) {
        const uint32_t kb_ = kstage(s);
        const uint32_t vb_ = kb_ + (uint32_t)(128 * QS) * 4;
        const int kv0 = kt * 128;
#pragma unroll
        for (int p = 0; p < 4; p++) {
            const int slot = tid + p * 256;
            const int r = slot >> 3, g = slot & 7;
            const __half* src = qkv + (size_t)(b * T + kv0 + r) * QKV3 + h * D + g * 8;
            const uint32_t doff = (uint32_t)(r * QS + g * 4) * 4;
            cp16(kb_ + doff, src + HD);
            cp16(vb_ + doff, src + 2 * HD);
        }
        CP_COMMIT();
    };

#pragma unroll 1
    for (int rep = 0; rep < 2; rep++) {
        const int qt = rep == 0 ? (NQT - 1 - blockIdx.x) : blockIdx.x;
        const int t0 = qt * 128;

        if (rep > 0) __syncthreads();   // protect Qs/stages from prior rep's readers

        // Load Q tile (scaled)
#pragma unroll
        for (int p = 0; p < 4; p++) {
            const int slot = tid + p * 256;
            const int r = slot >> 3, g = slot & 7;
            uint4 v = *(const uint4*)&qkv[(size_t)(b * T + t0 + r) * QKV3 + h * D + g * 8];
            __half2* hp = (__half2*)&v;
            hp[0] = __hmul2(hp[0], SC2); hp[1] = __hmul2(hp[1], SC2);
            hp[2] = __hmul2(hp[2], SC2); hp[3] = __hmul2(hp[3], SC2);
            *(uint4*)&Qs[r * QS + g * 4] = v;
        }

        float m0v = sink, m1v = sink, l0 = 1.f, l1 = 1.f;
        float o[8][4] = {};

        const int nkt = qt + 1;
        issue_kv(0, 0);

        for (int kt = 0; kt < nkt; kt++) {
            CP_WAIT0();
            __syncthreads();
            if (kt + 1 < nkt) issue_kv(kt + 1, (kt + 1) & 1);

            const uint32_t Kb = kstage(kt & 1);
            const uint32_t Vb = Kb + (uint32_t)(128 * QS) * 4;

#pragma unroll
            for (int c2 = 0; c2 < 2; c2++) {
                const int kb = kt * 128 + c2 * 64;
                if (kb > t0 + mb + 15) continue;
                const uint32_t Kc = Kb + (uint32_t)(c2 * 64 * QS) * 4;
                const uint32_t Vc = Vb + (uint32_t)(c2 * 64 * QS) * 4;

                float s[8][4] = {};
#pragma unroll
                for (int c = 0; c < 4; c++) {
                    uint32_t a0, a1, a2, a3;
                    ldsm_x4(a0, a1, a2, a3,
                            sbase + qoff + (uint32_t)((mb * QS + c * 8) * 4));
#pragma unroll
                    for (int jj = 0; jj < 4; jj++) {
                        uint32_t b0, b1, b2, b3;
                        ldsm_x4(b0, b1, b2, b3,
                                Kc + koff + (uint32_t)((jj * 16 * QS + c * 8) * 4));
                        mma16(s[2 * jj][0], s[2 * jj][1], s[2 * jj][2], s[2 * jj][3],
                              a0, a1, a2, a3, b0, b1);
                        mma16(s[2 * jj + 1][0], s[2 * jj + 1][1], s[2 * jj + 1][2], s[2 * jj + 1][3],
                              a0, a1, a2, a3, b2, b3);
                    }
                }

                if (kb + 63 > t0 + mb) {
                    const int qr0 = t0 + mb + lr, qr1 = qr0 + 8;
#pragma unroll
                    for (int j = 0; j < 8; j++) {
                        const int c = kb + j * 8 + 2 * lc;
                        if (c     > qr0) s[j][0] = -1e30f;
                        if (c + 1 > qr0) s[j][1] = -1e30f;
                        if (c     > qr1) s[j][2] = -1e30f;
                        if (c + 1 > qr1) s[j][3] = -1e30f;
                    }
                }

                float rmax0 = -1e30f, rmax1 = -1e30f;
#pragma unroll
                for (int j = 0; j < 8; j++) {
                    rmax0 = fmaxf(rmax0, fmaxf(s[j][0], s[j][1]));
                    rmax1 = fmaxf(rmax1, fmaxf(s[j][2], s[j][3]));
                }
                rmax0 = fmaxf(rmax0, __shfl_xor_sync(~0u, rmax0, 1));
                rmax0 = fmaxf(rmax0, __shfl_xor_sync(~0u, rmax0, 2));
                rmax1 = fmaxf(rmax1, __shfl_xor_sync(~0u, rmax1, 1));
                rmax1 = fmaxf(rmax1, __shfl_xor_sync(~0u, rmax1, 2));

                const float mn0 = fmaxf(m0v, rmax0), mn1 = fmaxf(m1v, rmax1);
                const float sc0 = __expf(m0v - mn0), sc1 = __expf(m1v - mn1);
                float rs0 = 0.f, rs1 = 0.f;
#pragma unroll
                for (int j = 0; j < 8; j++) {
                    s[j][0] = __expf(s[j][0] - mn0);
                    s[j][1] = __expf(s[j][1] - mn0);
                    s[j][2] = __expf(s[j][2] - mn1);
                    s[j][3] = __expf(s[j][3] - mn1);
                    rs0 += s[j][0] + s[j][1];
                    rs1 += s[j][2] + s[j][3];
                }
                rs0 += __shfl_xor_sync(~0u, rs0, 1); rs0 += __shfl_xor_sync(~0u, rs0, 2);
                rs1 += __shfl_xor_sync(~0u, rs1, 1); rs1 += __shfl_xor_sync(~0u, rs1, 2);
                l0 = l0 * sc0 + rs0;  l1 = l1 * sc1 + rs1;
                m0v = mn0;  m1v = mn1;

                uint32_t pa[4][4];
#pragma unroll
                for (int u = 0; u < 4; u++) {
                    pa[u][0] = packh2(s[2 * u][0],     s[2 * u][1]);
                    pa[u][1] = packh2(s[2 * u][2],     s[2 * u][3]);
                    pa[u][2] = packh2(s[2 * u + 1][0], s[2 * u + 1][1]);
                    pa[u][3] = packh2(s[2 * u + 1][2], s[2 * u + 1][3]);
                }

#pragma unroll
                for (int j = 0; j < 8; j++) {
                    o[j][0] *= sc0; o[j][1] *= sc0;
                    o[j][2] *= sc1; o[j][3] *= sc1;
                }

#pragma unroll
                for (int u = 0; u < 4; u++) {
#pragma unroll
                    for (int dd = 0; dd < 4; dd++) {
                        uint32_t b0, b1, b2, b3;
                        ldsm_x4_t(b0, b1, b2, b3,
                            Vc + (uint32_t)(((u * 16 + (sub & 1) * 8 + l8) * QS) * 4
                                            + (dd * 16 + (sub >> 1) * 8) * 2));
                        mma16(o[2 * dd][0], o[2 * dd][1], o[2 * dd][2], o[2 * dd][3],
                              pa[u][0], pa[u][1], pa[u][2], pa[u][3], b0, b1);
                        mma16(o[2 * dd + 1][0], o[2 * dd + 1][1], o[2 * dd + 1][2], o[2 * dd + 1][3],
                              pa[u][0], pa[u][1], pa[u][2], pa[u][3], b2, b3);
                    }
                }
            }
        }

        // Epilogue for this q-tile
        const float inv0 = 1.f / l0, inv1 = 1.f / l1;
#pragma unroll
        for (int j = 0; j < 8; j++) {
            const int c = h * D + j * 8 + 2 * lc;
            __half2 h0 = __floats2half2_rn(o[j][0] * inv0, o[j][1] * inv0);
            *(__half2*)&attn_out[(size_t)(b * T + t0 + mb + lr) * HD + c] = h0;
            __half2 h1 = __floats2half2_rn(o[j][2] * inv1, o[j][3] * inv1);
            *(__half2*)&attn_out[(size_t)(b * T + t0 + mb + 8 + lr) * HD + c] = h1;
        }
    }
}

// ---------------------------------------------------------------------------
// Launch
// ---------------------------------------------------------------------------
extern "C" void kernel_launch(void* const* d_in, const int* in_sizes, int n_in,
                              void* d_out, int out_size)
{
    const float* x      = (const float*)d_in[0];
    const float* W_qkv  = (const float*)d_in[1];
    const float* b_qkv  = (const float*)d_in[2];
    const float* W_proj = (const float*)d_in[3];
    const float* b_proj = (const float*)d_in[4];
    const float* sink   = (const float*)d_in[5];
    float* out = (float*)d_out;

    __half *xh, *wqh, *wph, *qkvh, *attnh;
    cudaGetSymbolAddress((void**)&xh,    g_xh);
    cudaGetSymbolAddress((void**)&wqh,   g_wqh);
    cudaGetSymbolAddress((void**)&wph,   g_wph);
    cudaGetSymbolAddress((void**)&qkvh,  g_qkvh);
    cudaGetSymbolAddress((void**)&attnh, g_attnh);

    cudaFuncSetAttribute((const void*)gemm_f16<true>,
                         cudaFuncAttributeMaxDynamicSharedMemorySize, GEMM_SMEM);
    cudaFuncSetAttribute((const void*)gemm_f16<false>,
                         cudaFuncAttributeMaxDynamicSharedMemorySize, GEMM_SMEM);
    cudaFuncSetAttribute(attn_f16,
                         cudaFuncAttributeMaxDynamicSharedMemorySize, ATTN_SMEM);

    // 0) fused fp32 -> fp16 conversions
    cvt_all<<<2048, 256>>>(x, xh, W_qkv, wqh, W_proj, wph);

    // 1) QKV GEMM (fp16 in/out): BK=32, 8 warps/CTA (R14 best)
    gemm_f16<true><<<dim3(QKV3 / 128, M_ROWS / 128), 256, GEMM_SMEM>>>(
        M_ROWS, QKV3, Cc, xh, wqh, b_qkv, qkvh);

    // 2) Flash attention with sink, cost-paired CTAs (256 uniform CTAs)
    attn_f16<<<dim3(T / 256, H, Bb), 256, ATTN_SMEM>>>(qkvh, sink, attnh);

    // 3) Proj GEMM (fp16 in, fp32 out): BK=32, 8 warps/CTA
    gemm_f16<false><<<dim3(HD / 128, M_ROWS / 128), 256, GEMM_SMEM>>>(
        M_ROWS, HD, HD, attnh, wph, b_proj, out);
}